// round 1
// baseline (speedup 1.0000x reference)
#include <cuda_runtime.h>
#include <math.h>
#include <stdint.h>

// Problem constants (fixed by the dataset)
#define NN 50000
#define EE 500000
#define FF 64
#define HH 4
#define HF 256          // H*F
#define TOT (EE + NN)   // edges + self loops
#define EPW 4           // edges per warp batch in k_alpha

// ---------------- device scratch (static globals: no allocation in kernel_launch) ----
__device__ float    g_xl[NN * HF];       // x @ W_l + b_l   [N,256]
__device__ float    g_xr[NN * HF];       // x @ W_r + b_r   [N,256]
__device__ float    g_loop[NN * FF];     // per-dst edge_attr sum -> mean (in place)
__device__ float    g_cnt[NN];           // in-degree counts
__device__ float    g_alpha[(size_t)TOT * HH]; // raw alpha -> exp(alpha-max) in place
__device__ unsigned g_amax[NN * HH];     // monotonic-uint encoded segment max
__device__ float    g_denom[NN * HH];    // softmax denominators
__device__ float    g_outpre[NN * FF];   // head-mean aggregation accumulator
__device__ float    g_bnsum[FF];
__device__ float    g_bnsq[FF];

// ---------------- helpers ----------------
__device__ __forceinline__ unsigned fenc(float f) {
    unsigned u = __float_as_uint(f);
    return (u & 0x80000000u) ? ~u : (u | 0x80000000u);
}
__device__ __forceinline__ float fdec(unsigned u) {
    return (u & 0x80000000u) ? __uint_as_float(u & 0x7fffffffu)
                             : __uint_as_float(~u);
}
__device__ __forceinline__ void red2(float* p, float a, float b) {
    unsigned long long gp = __cvta_generic_to_global(p);
    asm volatile("red.global.add.v2.f32 [%0], {%1, %2};"
                 :: "l"(gp), "f"(a), "f"(b) : "memory");
}
__device__ __forceinline__ float lrelu(float v) {
    return v > 0.f ? v : 0.2f * v;
}

// ---------------- K0: zero accumulators ----------------
__global__ void k_zero() {
    int i = blockIdx.x * blockDim.x + threadIdx.x;
    if (i < NN * FF) { g_loop[i] = 0.f; g_outpre[i] = 0.f; }
    if (i < NN * HH) { g_amax[i] = 0u; g_denom[i] = 0.f; }
    if (i < NN)      { g_cnt[i] = 0.f; }
    if (i < FF)      { g_bnsum[i] = 0.f; g_bnsq[i] = 0.f; }
}

// ---------------- K1: x_l / x_r linear (tiled GEMM [N,64]x[64,256] twice) ----------
// grid: (ceil(N/32), 4). blockIdx.y selects 128-column tile of the 512 output cols
// (0..255 -> W_l/g_xl, 256..511 -> W_r/g_xr).
__global__ void __launch_bounds__(256) k_lin(
    const float* __restrict__ x,
    const float* __restrict__ Wl, const float* __restrict__ bl,
    const float* __restrict__ Wr, const float* __restrict__ br)
{
    __shared__ float xs[32 * 64];
    __shared__ float ws[64 * 128];
    int tid  = threadIdx.x;
    int row0 = blockIdx.x * 32;
    int cb   = blockIdx.y * 128;     // 0,128,256,384
    const float* W = (cb < 256) ? Wl : Wr;
    const float* B = (cb < 256) ? bl : br;
    float*       D = (cb < 256) ? g_xl : g_xr;
    int wcb = cb & 255;

    for (int i = tid; i < 32 * 64; i += 256) {
        int r = i >> 6, k = i & 63;
        int row = row0 + r;
        xs[i] = (row < NN) ? x[row * 64 + k] : 0.f;
    }
    for (int i = tid; i < 64 * 128; i += 256) {
        int k = i >> 7, c = i & 127;
        ws[i] = W[k * 256 + wcb + c];
    }
    __syncthreads();

    int tx = tid & 31, ty = tid >> 5;
    float acc[4][4];
#pragma unroll
    for (int rr = 0; rr < 4; rr++)
#pragma unroll
        for (int cc = 0; cc < 4; cc++) acc[rr][cc] = 0.f;

    for (int k = 0; k < 64; k++) {
        float b0 = ws[k * 128 + tx];
        float b1 = ws[k * 128 + tx + 32];
        float b2 = ws[k * 128 + tx + 64];
        float b3 = ws[k * 128 + tx + 96];
#pragma unroll
        for (int rr = 0; rr < 4; rr++) {
            float a = xs[(ty + 8 * rr) * 64 + k];
            acc[rr][0] += a * b0;
            acc[rr][1] += a * b1;
            acc[rr][2] += a * b2;
            acc[rr][3] += a * b3;
        }
    }
#pragma unroll
    for (int rr = 0; rr < 4; rr++) {
        int row = row0 + ty + 8 * rr;
        if (row < NN) {
#pragma unroll
            for (int cc = 0; cc < 4; cc++) {
                int c = tx + 32 * cc;
                D[row * 256 + wcb + c] = acc[rr][cc] + B[wcb + c];
            }
        }
    }
}

// ---------------- K2: self-loop edge_attr sums + in-degree counts ----------------
__global__ void k_loopstats(const int* __restrict__ ei, const float* __restrict__ ea) {
    int gw   = (blockIdx.x * blockDim.x + threadIdx.x) >> 5;
    int lane = threadIdx.x & 31;
    if (gw >= EE) return;
    int dst = ei[EE + gw];
    const float* a = ea + (size_t)gw * 64;
    float2 v = *(const float2*)(a + lane * 2);
    red2(&g_loop[dst * 64 + lane * 2], v.x, v.y);
    if (lane == 0) atomicAdd(&g_cnt[dst], 1.0f);
}

// ---------------- K2b: loop_attr = sum / max(cnt, 1) ----------------
__global__ void k_loopfin() {
    int i = blockIdx.x * blockDim.x + threadIdx.x;
    if (i >= NN * FF) return;
    int n = i >> 6;
    float c = g_cnt[n];
    c = (c < 1.f) ? 1.f : c;
    g_loop[i] = g_loop[i] / c;
}

// ---------------- K3a: per-edge attention scores + segment max ----------------
// Persistent blocks; W_e + att cached in smem; each warp batches EPW edges so one
// W_e smem read feeds EPW FMAs.
extern __shared__ float k3a_sm[];
__global__ void __launch_bounds__(256) k_alpha(
    const int* __restrict__ ei, const float* __restrict__ ea,
    const float* __restrict__ We, const float* __restrict__ att)
{
    float* ws    = k3a_sm;                 // 64*256
    float* att_s = k3a_sm + 64 * 256;      // 256
    float* ea_s  = att_s + 256;            // 8 * EPW * 64
    int tid = threadIdx.x;
    for (int i = tid; i < 64 * 256; i += 256) ws[i] = We[i];
    if (tid < 256) att_s[tid] = att[tid];
    __syncthreads();

    int lane = tid & 31, wid = tid >> 5;
    float* myea = ea_s + wid * (EPW * 64);
    int gw = blockIdx.x * 8 + wid;
    int nw = gridDim.x * 8;

    for (int e0 = gw * EPW; e0 < TOT; e0 += nw * EPW) {
        int srcs[EPW], dsts[EPW];
#pragma unroll
        for (int q = 0; q < EPW; q++) {
            int e = e0 + q;
            if (e >= TOT) e = TOT - 1;
            const float* ap;
            int s, d;
            if (e < EE) { s = ei[e]; d = ei[EE + e]; ap = ea + (size_t)e * 64; }
            else        { s = d = e - EE;            ap = g_loop + (size_t)(e - EE) * 64; }
            srcs[q] = s; dsts[q] = d;
            myea[q * 64 + lane]      = ap[lane];
            myea[q * 64 + 32 + lane] = ap[32 + lane];
        }
        __syncwarp();

        float acc[EPW][8];
#pragma unroll
        for (int q = 0; q < EPW; q++)
#pragma unroll
            for (int j = 0; j < 8; j++) acc[q][j] = 0.f;

        for (int k = 0; k < 64; k++) {
            float4 w0 = *(const float4*)(ws + k * 256 + lane * 4);
            float4 w1 = *(const float4*)(ws + k * 256 + 128 + lane * 4);
#pragma unroll
            for (int q = 0; q < EPW; q++) {
                float ev = myea[q * 64 + k];
                acc[q][0] += ev * w0.x; acc[q][1] += ev * w0.y;
                acc[q][2] += ev * w0.z; acc[q][3] += ev * w0.w;
                acc[q][4] += ev * w1.x; acc[q][5] += ev * w1.y;
                acc[q][6] += ev * w1.z; acc[q][7] += ev * w1.w;
            }
        }

        float4 av0 = *(const float4*)(att_s + lane * 4);
        float4 av1 = *(const float4*)(att_s + 128 + lane * 4);
#pragma unroll
        for (int q = 0; q < EPW; q++) {
            int e = e0 + q;
            const float* xl = g_xl + (size_t)srcs[q] * 256;
            const float* xr = g_xr + (size_t)dsts[q] * 256;
            float4 l0 = *(const float4*)(xl + lane * 4);
            float4 l1 = *(const float4*)(xl + 128 + lane * 4);
            float4 r0 = *(const float4*)(xr + lane * 4);
            float4 r1 = *(const float4*)(xr + 128 + lane * 4);
            float m0 = lrelu(acc[q][0] + l0.x + r0.x);
            float m1 = lrelu(acc[q][1] + l0.y + r0.y);
            float m2 = lrelu(acc[q][2] + l0.z + r0.z);
            float m3 = lrelu(acc[q][3] + l0.w + r0.w);
            float m4 = lrelu(acc[q][4] + l1.x + r1.x);
            float m5 = lrelu(acc[q][5] + l1.y + r1.y);
            float m6 = lrelu(acc[q][6] + l1.z + r1.z);
            float m7 = lrelu(acc[q][7] + l1.w + r1.w);
            float p0 = m0 * av0.x + m1 * av0.y + m2 * av0.z + m3 * av0.w;
            float p1 = m4 * av1.x + m5 * av1.y + m6 * av1.z + m7 * av1.w;
#pragma unroll
            for (int o = 8; o >= 1; o >>= 1) {
                p0 += __shfl_xor_sync(0xffffffffu, p0, o);
                p1 += __shfl_xor_sync(0xffffffffu, p1, o);
            }
            // lanes 0 and 16 hold the reduced sums for heads {0,2} and {1,3}
            if (e < TOT && (lane == 0 || lane == 16)) {
                int h = lane >> 4;
                int d = dsts[q];
                g_alpha[(size_t)e * 4 + h]     = p0;
                g_alpha[(size_t)e * 4 + 2 + h] = p1;
                atomicMax(&g_amax[d * 4 + h],     fenc(p0));
                atomicMax(&g_amax[d * 4 + 2 + h], fenc(p1));
            }
        }
        __syncwarp();
    }
}

// ---------------- K3b: exp(alpha - max) and denominator ----------------
__global__ void k_exp(const int* __restrict__ ei) {
    int e = blockIdx.x * blockDim.x + threadIdx.x;
    if (e >= TOT) return;
    int d = (e < EE) ? ei[EE + e] : (e - EE);
    float4 a = *(const float4*)&g_alpha[(size_t)e * 4];
    uint4 mu = *(const uint4*)&g_amax[d * 4];
    float e0 = __expf(a.x - fdec(mu.x));
    float e1 = __expf(a.y - fdec(mu.y));
    float e2 = __expf(a.z - fdec(mu.z));
    float e3 = __expf(a.w - fdec(mu.w));
    float4 r; r.x = e0; r.y = e1; r.z = e2; r.w = e3;
    *(float4*)&g_alpha[(size_t)e * 4] = r;
    red2(&g_denom[d * 4],     e0, e1);
    red2(&g_denom[d * 4 + 2], e2, e3);
}

// ---------------- K3c: weighted aggregation, fused head-mean ----------------
__global__ void k_agg(const int* __restrict__ ei) {
    int gw   = (blockIdx.x * blockDim.x + threadIdx.x) >> 5;
    int lane = threadIdx.x & 31;
    if (gw >= TOT) return;
    int s, d;
    if (gw < EE) { s = ei[gw]; d = ei[EE + gw]; }
    else         { s = d = gw - EE; }
    float4 ex = *(const float4*)&g_alpha[(size_t)gw * 4];
    float4 dn = *(const float4*)&g_denom[d * 4];
    float w0 = 0.25f * ex.x / (dn.x + 1e-16f);
    float w1 = 0.25f * ex.y / (dn.y + 1e-16f);
    float w2 = 0.25f * ex.z / (dn.z + 1e-16f);
    float w3 = 0.25f * ex.w / (dn.w + 1e-16f);
    const float* xl = g_xl + (size_t)s * 256;
    int f2 = lane * 2;
    float2 v0 = *(const float2*)(xl + f2);
    float2 v1 = *(const float2*)(xl + 64 + f2);
    float2 v2 = *(const float2*)(xl + 128 + f2);
    float2 v3 = *(const float2*)(xl + 192 + f2);
    float c0 = w0 * v0.x + w1 * v1.x + w2 * v2.x + w3 * v3.x;
    float c1 = w0 * v0.y + w1 * v1.y + w2 * v2.y + w3 * v3.y;
    red2(&g_outpre[d * 64 + f2], c0, c1);
}

// ---------------- K4a: BN statistics ----------------
__global__ void __launch_bounds__(256) k_bnstats(const float* __restrict__ bias) {
    int tid = threadIdx.x;
    int f = tid & 63, rg = tid >> 6;
    float b = bias[f];
    float s = 0.f, s2 = 0.f;
    for (int r = blockIdx.x * 4 + rg; r < NN; r += gridDim.x * 4) {
        float v = g_outpre[r * 64 + f] + b;
        s += v; s2 += v * v;
    }
    __shared__ float sh[2][4][64];
    sh[0][rg][f] = s;
    sh[1][rg][f] = s2;
    __syncthreads();
    if (tid < 64) {
        float ts = sh[0][0][tid] + sh[0][1][tid] + sh[0][2][tid] + sh[0][3][tid];
        float tq = sh[1][0][tid] + sh[1][1][tid] + sh[1][2][tid] + sh[1][3][tid];
        atomicAdd(&g_bnsum[tid], ts);
        atomicAdd(&g_bnsq[tid], tq);
    }
}

// ---------------- K4b: BN apply + ReLU ----------------
__global__ void k_bnapply(const float* __restrict__ bias,
                          const float* __restrict__ gamma,
                          const float* __restrict__ beta,
                          float* __restrict__ out) {
    int i = blockIdx.x * blockDim.x + threadIdx.x;
    if (i >= NN * FF) return;
    int f = i & 63;
    const float invn = 1.0f / (float)NN;
    float mu  = g_bnsum[f] * invn;
    float var = g_bnsq[f] * invn - mu * mu;
    float v = g_outpre[i] + bias[f];
    float o = gamma[f] * (v - mu) * rsqrtf(var + 1e-5f) + beta[f];
    out[i] = (o > 0.f) ? o : 0.f;
}

// ---------------- launch ----------------
extern "C" void kernel_launch(void* const* d_in, const int* in_sizes, int n_in,
                              void* d_out, int out_size) {
    const float* x     = (const float*)d_in[0];
    const int*   ei    = (const int*)d_in[1];
    const float* ea    = (const float*)d_in[2];
    const float* Wl    = (const float*)d_in[3];
    const float* bl    = (const float*)d_in[4];
    const float* Wr    = (const float*)d_in[5];
    const float* br    = (const float*)d_in[6];
    const float* We    = (const float*)d_in[7];
    const float* att   = (const float*)d_in[8];
    const float* bias  = (const float*)d_in[9];
    const float* gamma = (const float*)d_in[10];
    const float* beta  = (const float*)d_in[11];
    float* out = (float*)d_out;

    const int K3A_SMEM = (64 * 256 + 256 + 8 * EPW * 64) * (int)sizeof(float); // 74752
    cudaFuncSetAttribute(k_alpha, cudaFuncAttributeMaxDynamicSharedMemorySize, K3A_SMEM);

    k_zero<<<(NN * FF + 255) / 256, 256>>>();

    dim3 g1((NN + 31) / 32, 4);
    k_lin<<<g1, 256>>>(x, Wl, bl, Wr, br);

    k_loopstats<<<(EE * 32 + 255) / 256, 256>>>(ei, ea);
    k_loopfin<<<(NN * FF + 255) / 256, 256>>>();

    k_alpha<<<296, 256, K3A_SMEM>>>(ei, ea, We, att);
    k_exp<<<(TOT + 255) / 256, 256>>>(ei);
    k_agg<<<((size_t)TOT * 32 + 255) / 256, 256>>>(ei);

    k_bnstats<<<128, 256>>>(bias);
    k_bnapply<<<(NN * FF + 255) / 256, 256>>>(bias, gamma, beta, out);
}